// round 1
// baseline (speedup 1.0000x reference)
#include <cuda_runtime.h>

// Problem constants
#define BB   8
#define ND   12288
#define NU   49152
#define CI   64
#define CO   32
#define SP   9
#define NNZE 147456
#define KTOT (SP * CI)   // 576

// Scratch: pooled intermediate [B, N_UP, C_IN] fp32 = 100.7 MB
__device__ float g_pooled[(size_t)BB * NU * CI];

// ---------------------------------------------------------------------------
// Kernel 0: zero the pooled buffer (float4 stores, exact grid)
// ---------------------------------------------------------------------------
__global__ void zero_pooled() {
    int i = blockIdx.x * blockDim.x + threadIdx.x;
    if (i < (BB * NU * CI) / 4)
        reinterpret_cast<float4*>(g_pooled)[i] = make_float4(0.f, 0.f, 0.f, 0.f);
}

// ---------------------------------------------------------------------------
// Kernel 1: sparse scatter-add pooling.
// Thread = (nnz entry e, channel c). Warp shares one e -> x loads and RED
// destinations are contiguous 128B segments. Loops over batch inside.
// ---------------------------------------------------------------------------
__global__ void scatter_pool(const float* __restrict__ x,
                             const int*   __restrict__ rows,
                             const int*   __restrict__ cols,
                             const float* __restrict__ vals) {
    int t = blockIdx.x * blockDim.x + threadIdx.x;
    if (t >= NNZE * CI) return;
    int e = t >> 6;
    int c = t & 63;
    int row = __ldg(rows + e);
    int col = __ldg(cols + e);
    float v  = __ldg(vals + e);
#pragma unroll
    for (int b = 0; b < BB; b++) {
        float xv = __ldg(x + ((size_t)b * ND + col) * CI + c);
        atomicAdd(g_pooled + ((size_t)b * NU + row) * CI + c, xv * v);
    }
}

// ---------------------------------------------------------------------------
// Kernel 2: fused spiral gather + GEMM + bias + relu.
// Block tile: 128 rows x 32 outs. Thread tile: 4 rows x 4 outs, accumulated
// in packed f32x2 pairs via fma.rn.f32x2 (2 FMAs per fma-pipe issue slot).
// W transposed in smem [576][32] (broadcast, conflict-free).
// Gathered A tile [128][GPAD=65] per spiral step (row-group bank offsets 0/4/8/12).
// ---------------------------------------------------------------------------
#define TILE_R 128
#define GPAD   65

__device__ __forceinline__ float2 ffma2(float a, float2 w, float2 c) {
    float2 r;
    asm("{\n\t"
        ".reg .b64 ra, rb, rc, rd;\n\t"
        "mov.b64 ra, {%2, %2};\n\t"
        "mov.b64 rb, {%3, %4};\n\t"
        "mov.b64 rc, {%5, %6};\n\t"
        "fma.rn.f32x2 rd, ra, rb, rc;\n\t"
        "mov.b64 {%0, %1}, rd;\n\t"
        "}"
        : "=f"(r.x), "=f"(r.y)
        : "f"(a), "f"(w.x), "f"(w.y), "f"(c.x), "f"(c.y));
    return r;
}

__global__ void __launch_bounds__(256, 2)
spiral_fused(const int*   __restrict__ sidx,
             const float* __restrict__ weight,
             const float* __restrict__ bias,
             float*       __restrict__ out) {
    extern __shared__ float sm[];
    float* Wt = sm;                  // [KTOT][CO] transposed weight, 73.7 KB
    float* G  = sm + KTOT * CO;      // [TILE_R][GPAD] gathered tile, 33.3 KB

    const int tid = threadIdx.x;
    const int b   = blockIdx.y;
    const int n0  = blockIdx.x * TILE_R;

    // Load W transposed: Wt[k][o] = weight[o][k]. Writes coalesced/conflict-free.
    for (int i = tid; i < KTOT * CO; i += 256) {
        int k = i >> 5;
        int o = i & 31;
        Wt[i] = __ldg(weight + o * KTOT + k);
    }

    const int to = tid & 7;     // out group: o0 = to*4
    const int tr = tid >> 3;    // row group: rows tr*4 .. tr*4+3
    const int o0 = to * 4;

    float2 acc[4][2];
#pragma unroll
    for (int i = 0; i < 4; i++) {
        acc[i][0] = make_float2(0.f, 0.f);
        acc[i][1] = make_float2(0.f, 0.f);
    }

    const float* pooledB = g_pooled + (size_t)b * NU * CI;

#pragma unroll 1
    for (int s = 0; s < SP; s++) {
        __syncthreads();   // protects G from previous iteration's readers
        // Gather 128 rows x 64 ch: 2048 float4 loads, 8 per thread.
#pragma unroll
        for (int it = 0; it < (TILE_R * 16) / 256; it++) {
            int i  = it * 256 + tid;
            int rl = i >> 4;
            int cv = (i & 15) << 2;
            int idx = __ldg(sidx + (n0 + rl) * SP + s);
            float4 v = *reinterpret_cast<const float4*>(pooledB + idx * CI + cv);
            float* gp = G + rl * GPAD + cv;
            gp[0] = v.x; gp[1] = v.y; gp[2] = v.z; gp[3] = v.w;
        }
        __syncthreads();

        const float* wk = Wt + s * CI * CO + o0;
        const float* gk = G + tr * 4 * GPAD;
#pragma unroll 4
        for (int kc = 0; kc < CI; kc++) {
            float2 w0 = *reinterpret_cast<const float2*>(wk + kc * CO);
            float2 w1 = *reinterpret_cast<const float2*>(wk + kc * CO + 2);
#pragma unroll
            for (int i = 0; i < 4; i++) {
                float g = gk[i * GPAD + kc];
                acc[i][0] = ffma2(g, w0, acc[i][0]);
                acc[i][1] = ffma2(g, w1, acc[i][1]);
            }
        }
    }

    // Epilogue: bias + relu, float4 stores (coalesced 128B segments).
    float4 bv = *reinterpret_cast<const float4*>(bias + o0);
#pragma unroll
    for (int i = 0; i < 4; i++) {
        float4 r;
        r.x = fmaxf(acc[i][0].x + bv.x, 0.f);
        r.y = fmaxf(acc[i][0].y + bv.y, 0.f);
        r.z = fmaxf(acc[i][1].x + bv.z, 0.f);
        r.w = fmaxf(acc[i][1].y + bv.w, 0.f);
        int n = n0 + tr * 4 + i;
        *reinterpret_cast<float4*>(out + ((size_t)b * NU + n) * CO + o0) = r;
    }
}

// ---------------------------------------------------------------------------
// Launch
// ---------------------------------------------------------------------------
extern "C" void kernel_launch(void* const* d_in, const int* in_sizes, int n_in,
                              void* d_out, int out_size) {
    const float* x        = (const float*)d_in[0];
    const int*   up_rows  = (const int*)  d_in[1];
    const int*   up_cols  = (const int*)  d_in[2];
    const float* up_vals  = (const float*)d_in[3];
    const int*   sidx     = (const int*)  d_in[4];
    const float* weight   = (const float*)d_in[5];
    const float* bias     = (const float*)d_in[6];
    float*       out      = (float*)d_out;

    zero_pooled<<<(BB * NU * CI / 4 + 255) / 256, 256>>>();
    scatter_pool<<<(NNZE * CI + 255) / 256, 256>>>(x, up_rows, up_cols, up_vals);

    int smem = (KTOT * CO + TILE_R * GPAD) * (int)sizeof(float);  // 104.5 KB
    cudaFuncSetAttribute(spiral_fused,
                         cudaFuncAttributeMaxDynamicSharedMemorySize, smem);
    dim3 grid(NU / TILE_R, BB);
    spiral_fused<<<grid, 256, smem>>>(sidx, weight, bias, out);
}